// round 15
// baseline (speedup 1.0000x reference)
#include <cuda_runtime.h>
#include <cuda_fp16.h>
#include <cstdint>

// Problem constants
#define B_  4
#define S_  2048
#define E_  512
#define Q_  8
#define F_  2048
#define M_  (B_ * S_)

// Tiling: CTA 64x128, warp tile 32x32 (2m x 4n warps), 3 CTAs/SM
#define BM 64
#define BN 128
#define NTH 256
#define NCHUNK (F_ / 32)      // 64

// ---- persistent scratch (fp16 packed as b32 pairs) ----
// W2P: B-fragment lane-major fp16 for BN=128. uint4 index:
//   (c*4 + n0blk)*512 + (wnb*2 + ks)*64 + r*32 + lane ; comp e = nt
//   k = c*32 + ks*16 + r*8 + 2t(+1), n = n0blk*128 + wnb*32 + nt*8 + g
__device__ uint32_t g_W2P[(size_t)F_ * E_ / 2];    // 2 MB
// HP: A-fragment lane-major fp16 (unchanged from round 14). uint4 index:
//   (m32blk*64 + c)*128 + (ks*2 + mt)*32 + lane
//   comp r: row = m32blk*32 + mt*16 + g + (r&1)*8, k = c*32+ks*16+(r>>1)*8+2t(+1)
__device__ uint32_t g_HP[(size_t)M_ * F_ / 2];     // 32 MB

// ---------------- helpers ----------------
__device__ __forceinline__ uint32_t pack_h2(float lo, float hi) {
    __half2 h = __floats2half2_rn(lo, hi);
    return *reinterpret_cast<uint32_t*>(&h);
}

// D(16x8,f32) += A(16x16,f16 row) * B(16x8,f16 col)
__device__ __forceinline__ void mma16(float* d, const uint32_t* a, const uint32_t* b) {
    asm volatile(
        "mma.sync.aligned.m16n8k16.row.col.f32.f16.f16.f32 "
        "{%0,%1,%2,%3}, {%4,%5,%6,%7}, {%8,%9}, {%0,%1,%2,%3};"
        : "+f"(d[0]), "+f"(d[1]), "+f"(d[2]), "+f"(d[3])
        : "r"(a[0]), "r"(a[1]), "r"(a[2]), "r"(a[3]), "r"(b[0]), "r"(b[1]));
}

// ---------------- prepass 1: W2 -> fp16 B-fragment order (BN=128) ----------------
// One thread per output b32 (k-pair). 2^19 threads.
__global__ void w2_permute_kernel(const float* __restrict__ W2) {
    const int idx = blockIdx.x * 256 + threadIdx.x;    // 0 .. 2^19-1
    const int e     = idx & 3;             // nt
    const int lane  = (idx >> 2) & 31;
    const int r     = (idx >> 7) & 1;
    const int ks    = (idx >> 8) & 1;
    const int wnb   = (idx >> 9) & 3;
    const int n0blk = (idx >> 11) & 3;
    const int c     = idx >> 13;

    const int g = lane >> 2;
    const int t = lane & 3;

    const int n = n0blk * 128 + wnb * 32 + e * 8 + g;
    const int k = c * 32 + ks * 16 + r * 8 + 2 * t;

    g_W2P[idx] = pack_h2(W2[(size_t)k * E_ + n], W2[(size_t)(k + 1) * E_ + n]);
}

// ---------------- prepass 2: H = relu(z@W1+b1) -> fp16 A-fragment order ----------------
// grid (M_/64, F_/128), block 256. Tile 64 rows x 128 k.
__global__ __launch_bounds__(256) void h_permute_kernel(
    const float* __restrict__ x, const float* __restrict__ theta,
    const float* __restrict__ W1, const float* __restrict__ b1) {
    __shared__ float hs[64 * 132];
    const int tid = threadIdx.x;
    const int m0  = blockIdx.x * 64;
    const int k0  = blockIdx.y * 128;
    const int hm  = tid & 63;
    const int kq  = tid >> 6;

    float zreg[Q_];
    {
        const float4 x0 = *(const float4*)(x + (size_t)(m0 + hm) * E_);
        const float4 x1 = *(const float4*)(x + (size_t)(m0 + hm) * E_ + 4);
        zreg[0] = cosf(theta[0]) * cosf(x0.x);
        zreg[1] = cosf(theta[1]) * cosf(x0.y);
        zreg[2] = cosf(theta[2]) * cosf(x0.z);
        zreg[3] = cosf(theta[3]) * cosf(x0.w);
        zreg[4] = cosf(theta[4]) * cosf(x1.x);
        zreg[5] = cosf(theta[5]) * cosf(x1.y);
        zreg[6] = cosf(theta[6]) * cosf(x1.z);
        zreg[7] = cosf(theta[7]) * cosf(x1.w);
    }

    #pragma unroll
    for (int c2 = 0; c2 < 8; c2++) {
        const int kk = kq * 32 + c2 * 4;
        const float4 b1v = *(const float4*)(b1 + k0 + kk);
        float h0 = b1v.x, h1 = b1v.y, h2 = b1v.z, h3 = b1v.w;
        #pragma unroll
        for (int q = 0; q < Q_; q++) {
            const float4 wv = *(const float4*)(W1 + (size_t)q * F_ + k0 + kk);
            h0 = fmaf(zreg[q], wv.x, h0);
            h1 = fmaf(zreg[q], wv.y, h1);
            h2 = fmaf(zreg[q], wv.z, h2);
            h3 = fmaf(zreg[q], wv.w, h3);
        }
        float4 o;
        o.x = fmaxf(h0, 0.0f);
        o.y = fmaxf(h1, 0.0f);
        o.z = fmaxf(h2, 0.0f);
        o.w = fmaxf(h3, 0.0f);
        *(float4*)(hs + hm * 132 + kk) = o;
    }
    __syncthreads();

    // permute-write: 1024 uint4 per tile, 4 per thread, coalesced STG.128
    uint4* HP4 = (uint4*)g_HP;
    #pragma unroll
    for (int rr = 0; rr < 4; rr++) {
        const int j    = tid + rr * 256;
        const int lane = j & 31;
        const int mt   = (j >> 5) & 1;
        const int ks   = (j >> 6) & 1;
        const int cc   = (j >> 7) & 3;
        const int m32  = (j >> 9) & 1;
        const int g    = lane >> 2;
        const int t    = lane & 3;

        uint4 v;
        uint32_t* vr = (uint32_t*)&v;
        #pragma unroll
        for (int r = 0; r < 4; r++) {
            const int row = m32 * 32 + mt * 16 + g + (r & 1) * 8;
            const int kk  = cc * 32 + ks * 16 + (r >> 1) * 8 + 2 * t;
            vr[r] = pack_h2(hs[row * 132 + kk], hs[row * 132 + kk + 1]);
        }
        const int m32g = blockIdx.x * 2 + m32;
        const int cg   = blockIdx.y * 4 + cc;
        HP4[(size_t)(m32g * 64 + cg) * 128 + (ks * 2 + mt) * 32 + lane] = v;
    }
}

// ---------------- main kernel: barrier-free gmem-fed fp16 GEMM, 32x32 warp tile ----------------
__global__ __launch_bounds__(NTH, 3)
void ffq_mma_kernel(const float* __restrict__ b2, float* __restrict__ out) {
    const int tid = threadIdx.x;
    const int w   = tid >> 5;
    const int l   = tid & 31;
    const int m0  = blockIdx.x * BM;
    const int n0  = blockIdx.y * BN;

    // warp tile: 2 (m) x 4 (n); WM=32, WN=32
    const int wm  = (w & 1) * 32;
    const int wn  = (w >> 1) * 32;
    const int wnb = w >> 1;
    const int m32blk = blockIdx.x * 2 + (w & 1);

    const int g = l >> 2;
    const int t = l & 3;

    // A: uint4 base; per chunk +128; (ks, mt) -> +ks*64 + mt*32
    const uint4* Ab = (const uint4*)g_HP + (size_t)m32blk * 8192 + l;
    // B: uint4 base; per chunk +2048; (ks, r) -> +ks*64 + r*32
    const uint4* Bb = (const uint4*)g_W2P + (size_t)blockIdx.y * 512
                    + (size_t)wnb * 128 + l;

    float acc[2][4][4];
    #pragma unroll
    for (int mt = 0; mt < 2; mt++)
        #pragma unroll
        for (int nt = 0; nt < 4; nt++)
            #pragma unroll
            for (int v = 0; v < 4; v++) acc[mt][nt][v] = 0.0f;

    // ---- prime pipeline with (c=0, ks=0) ----
    uint4 av0 = Ab[0];
    uint4 av1 = Ab[32];
    uint4 q0  = Bb[0];
    uint4 q1  = Bb[32];

    for (int c = 0; c < NCHUNK; c++) {
        #pragma unroll
        for (int ks = 0; ks < 2; ks++) {
            const uint4 cav0 = av0, cav1 = av1;
            const uint4 cq0 = q0, cq1 = q1;

            // prefetch next (c, ks+1) / (c+1, 0)
            const int last = (c == NCHUNK - 1) && (ks == 1);
            if (!last) {
                const int nc  = (ks == 1) ? c + 1 : c;
                const int nks = ks ^ 1;
                const uint4* An = Ab + (size_t)nc * 128 + nks * 64;
                const uint4* Bn = Bb + (size_t)nc * 2048 + nks * 64;
                av0 = An[0];
                av1 = An[32];
                q0  = Bn[0];
                q1  = Bn[32];
            }

            uint32_t a[2][4];
            a[0][0] = cav0.x; a[0][1] = cav0.y; a[0][2] = cav0.z; a[0][3] = cav0.w;
            a[1][0] = cav1.x; a[1][1] = cav1.y; a[1][2] = cav1.z; a[1][3] = cav1.w;
            // bf[nt] = {q0.comp[nt], q1.comp[nt]} (r = 0, 1)
            uint32_t bf[4][2];
            bf[0][0] = cq0.x; bf[1][0] = cq0.y; bf[2][0] = cq0.z; bf[3][0] = cq0.w;
            bf[0][1] = cq1.x; bf[1][1] = cq1.y; bf[2][1] = cq1.z; bf[3][1] = cq1.w;

            #pragma unroll
            for (int mt = 0; mt < 2; mt++)
                #pragma unroll
                for (int nt = 0; nt < 4; nt++)
                    mma16(acc[mt][nt], a[mt], bf[nt]);
        }
    }

    // ---- epilogue: add b2, store ----
    {
        #pragma unroll
        for (int nt = 0; nt < 4; nt++) {
            const int col = n0 + wn + nt * 8 + t * 2;
            const float2 bb = *(const float2*)(b2 + col);
            #pragma unroll
            for (int mt = 0; mt < 2; mt++) {
                const int r0 = m0 + wm + mt * 16 + g;
                float2 v0, v1;
                v0.x = acc[mt][nt][0] + bb.x;
                v0.y = acc[mt][nt][1] + bb.y;
                v1.x = acc[mt][nt][2] + bb.x;
                v1.y = acc[mt][nt][3] + bb.y;
                *(float2*)(out + (size_t)r0 * E_ + col)       = v0;
                *(float2*)(out + (size_t)(r0 + 8) * E_ + col) = v1;
            }
        }
    }
}

extern "C" void kernel_launch(void* const* d_in, const int* in_sizes, int n_in,
                              void* d_out, int out_size) {
    // Identify inputs by element count (order-proof; all sizes distinct)
    const float *x = nullptr, *theta = nullptr, *W1 = nullptr,
                *b1 = nullptr, *W2 = nullptr, *b2 = nullptr;
    for (int i = 0; i < n_in; i++) {
        switch (in_sizes[i]) {
            case B_ * S_ * E_: x     = (const float*)d_in[i]; break;
            case F_ * E_:      W2    = (const float*)d_in[i]; break;
            case Q_ * F_:      W1    = (const float*)d_in[i]; break;
            case F_:           b1    = (const float*)d_in[i]; break;
            case E_:           b2    = (const float*)d_in[i]; break;
            case Q_:           theta = (const float*)d_in[i]; break;
            default: break;
        }
    }
    float* out = (float*)d_out;

    // prepass 1: W2 -> fp16 B-fragment order (2 MB, L2-resident)
    w2_permute_kernel<<<(F_ * E_ / 2) / 256, 256>>>(W2);
    // prepass 2: H -> fp16 A-fragment order (32 MB)
    h_permute_kernel<<<dim3(M_ / 64, F_ / 128), 256>>>(x, theta, W1, b1);

    // main: barrier-free streamed fp16 GEMM, 24 warps/SM
    dim3 grid(M_ / BM, E_ / BN);   // 128 x 4 = 512 CTAs, 3 CTAs/SM
    ffq_mma_kernel<<<grid, NTH>>>(b2, out);
}